// round 8
// baseline (speedup 1.0000x reference)
#include <cuda_runtime.h>
#include <cstdint>

// Problem constants
#define B_       512
#define P_       65536
#define NOUT_    512
#define COUT_    4
#define NCLS_    10

// Work decomposition: 2048 units = 128 slices (512 p) x 16 row-groups (32 rows)
#define SLICES   128
#define SLICE_P  512
#define TILE_P   128
#define TPU      4                    // tiles per unit
#define UNITS    2048
#define GRIDM    296                  // persistent blocks (2 per SM on 148 SMs)
#define ROWS_    32
#define XSTRIDE  132                  // smem row stride in floats (conflict-free LDS.128)
#define WPAD     12
#define DEPTH    4                    // cp.async stages

// Dynamic smem layout for main: [xs(4) | wsm | segb(4) | red]
#define XBUF_FLOATS (ROWS_ * XSTRIDE)                  // 4224
#define XS_BYTES    (DEPTH * XBUF_FLOATS * 4)          // 67584
#define WSM_BYTES   (NOUT_ * WPAD * 4)                 // 24576
#define SEGB_BYTES  (DEPTH * TILE_P * 4)               // 2048
#define RED_BYTES   (256 * NCLS_ * 4)                  // 10240
#define SMEM_TOTAL  (XS_BYTES + WSM_BYTES + SEGB_BYTES + RED_BYTES)  // 104448

// Scratch (allocation-free: __device__ global)
__device__ float g_partial[SLICES * B_ * NCLS_];  // [128][512][10], 2.62 MB

__device__ __forceinline__ uint32_t smem_u32(const void* p) {
    return (uint32_t)__cvta_generic_to_shared(p);
}
__device__ __forceinline__ void cp16(void* smem, const void* gmem) {
    uint32_t a = smem_u32(smem);
    asm volatile("cp.async.cg.shared.global [%0], [%1], 16;" :: "r"(a), "l"(gmem));
}
__device__ __forceinline__ unsigned long long packf2(float v) {
    unsigned long long r;
    asm("mov.b64 %0, {%1, %1};" : "=l"(r) : "f"(v));
    return r;
}

// ---------------------------------------------------------------------------
// Main (persistent): partial[s, n, k] = sum_{p in slice s} x[n,p]*Weff[seg[p]][k]
// Grid 296 blocks, block b owns units {b, b+296, ...} (7 or 6 units).
// Prologue: issue tile 0..2 cp.async, then compute Weff table (from W_fgl/W_fc,
// L2-resident after first block) into smem — kills the prep kernel.
// Flat tile pipeline streams ACROSS unit boundaries (seg staged per tile with
// its x tile); acc flushed to g_partial at each unit boundary.
// ---------------------------------------------------------------------------
__global__ void __launch_bounds__(256, 2)
fused_main_k(const float* __restrict__ x, const int* __restrict__ seg,
             const float* __restrict__ W_fgl, const float* __restrict__ W_fc) {
    extern __shared__ __align__(16) char dynsmem[];
    float* xs   = (float*)dynsmem;                                   // [4][4224]
    float* wsm  = (float*)(dynsmem + XS_BYTES);                      // [512*12]
    int*   segb = (int*)(dynsmem + XS_BYTES + WSM_BYTES);            // [4][128]
    float* red  = (float*)(dynsmem + XS_BYTES + WSM_BYTES + SEGB_BYTES); // [2560]

    const int t    = threadIdx.x;
    const int warp = t >> 5;
    const int lane = t & 31;
    const int b    = blockIdx.x;

    const int nU = (UNITS - b + GRIDM - 1) / GRIDM;   // 7 or 6
    const int nT = nU * TPU;

    auto stage = [&](int ft) {
        int buf = ft & (DEPTH - 1);
        int U   = b + (ft >> 2) * GRIDM;
        int s   = U & (SLICES - 1);
        int g   = U >> 7;
        int pOff = s * SLICE_P + (ft & 3) * TILE_P;
        const float* xb  = x + (size_t)(g * ROWS_) * P_ + pOff;
        float*       xsb = xs + buf * XBUF_FLOATS;
#pragma unroll
        for (int r = 0; r < 4; r++) {
            int f   = r * 256 + t;
            int row = f >> 5;              // 32 float4 per row
            int c4  = (f & 31) << 2;
            cp16(&xsb[row * XSTRIDE + c4], xb + (size_t)row * P_ + c4);
        }
        if (t < 32) cp16(&segb[buf * TILE_P + t * 4], seg + pOff + t * 4);
    };

    // Prologue: get DRAM streaming first, then build Weff (overlapped).
    stage(0); asm volatile("cp.async.commit_group;");
    stage(1); asm volatile("cp.async.commit_group;");
    stage(2); asm volatile("cp.async.commit_group;");

#pragma unroll
    for (int jj = 0; jj < 2; jj++) {
        int j = t + jj * 256;
        float w[NCLS_];
#pragma unroll
        for (int k = 0; k < NCLS_; k++) w[k] = 0.f;
#pragma unroll
        for (int c = 0; c < COUT_; c++) {
            int r = c * NOUT_ + j;
            float a = W_fgl[r];
            const float* wf = W_fc + r * NCLS_;
#pragma unroll
            for (int k = 0; k < NCLS_; k++) w[k] += a * wf[k];
        }
#pragma unroll
        for (int k = 0; k < NCLS_; k++) wsm[j * WPAD + k] = w[k];
    }
    // (first loop iteration's __syncthreads orders these STS before any reads)

    unsigned long long acc[5];
#pragma unroll
    for (int q = 0; q < 5; q++) acc[q] = 0ull;

    auto compute = [&](int buf) {
        const float4* xrow =
            (const float4*)&xs[buf * XBUF_FLOATS + lane * XSTRIDE + warp * 16];
        const int4* sp = (const int4*)&segb[buf * TILE_P + warp * 16];
#pragma unroll
        for (int step = 0; step < 4; step++) {
            float4 x4  = xrow[step];     // 4 pixels of this row (LDS.128)
            int4   sid = sp[step];       // 4 seg ids (uniform -> broadcast)
#pragma unroll
            for (int j = 0; j < 4; j++) {
                int   id = (j == 0) ? sid.x : (j == 1) ? sid.y : (j == 2) ? sid.z : sid.w;
                float xv = (j == 0) ? x4.x  : (j == 1) ? x4.y  : (j == 2) ? x4.z  : x4.w;
                const unsigned long long* wrow =
                    (const unsigned long long*)&wsm[id * WPAD];
                ulonglong2 wab = *(const ulonglong2*)(wrow);      // k0..3
                ulonglong2 wcd = *(const ulonglong2*)(wrow + 2);  // k4..7
                unsigned long long we = wrow[4];                   // k8..9
                unsigned long long xp = packf2(xv);
                asm("fma.rn.f32x2 %0, %1, %2, %0;" : "+l"(acc[0]) : "l"(xp), "l"(wab.x));
                asm("fma.rn.f32x2 %0, %1, %2, %0;" : "+l"(acc[1]) : "l"(xp), "l"(wab.y));
                asm("fma.rn.f32x2 %0, %1, %2, %0;" : "+l"(acc[2]) : "l"(xp), "l"(wcd.x));
                asm("fma.rn.f32x2 %0, %1, %2, %0;" : "+l"(acc[3]) : "l"(xp), "l"(wcd.y));
                asm("fma.rn.f32x2 %0, %1, %2, %0;" : "+l"(acc[4]) : "l"(xp), "l"(we));
            }
        }
    };

#pragma unroll 1
    for (int ft = 0; ft < nT; ft++) {
        asm volatile("cp.async.wait_group 2;");
        __syncthreads();
        if (ft + DEPTH - 1 < nT) stage(ft + DEPTH - 1);
        asm volatile("cp.async.commit_group;");   // possibly empty: uniform count
        compute(ft & (DEPTH - 1));

        if ((ft & 3) == 3) {
            // Unit boundary: deterministic cross-warp reduce -> g_partial, reset acc.
            int U = b + (ft >> 2) * GRIDM;
            int s = U & (SLICES - 1);
            int g = U >> 7;
#pragma unroll
            for (int q = 0; q < 5; q++) {
                float lo, hi;
                asm("mov.b64 {%0,%1}, %2;" : "=f"(lo), "=f"(hi) : "l"(acc[q]));
                red[t * NCLS_ + 2 * q]     = lo;
                red[t * NCLS_ + 2 * q + 1] = hi;
                acc[q] = 0ull;
            }
            __syncthreads();
            for (int i = t; i < ROWS_ * NCLS_; i += 256) {
                int row = i / NCLS_;
                int k   = i - row * NCLS_;
                float sum = 0.f;
#pragma unroll
                for (int w = 0; w < 8; w++) sum += red[(w * 32 + row) * NCLS_ + k];
                g_partial[((size_t)s * B_ + g * ROWS_ + row) * NCLS_ + k] = sum;
            }
            __syncthreads();   // red reads done before next unit's writes
        }
    }
}

// ---------------------------------------------------------------------------
// Finalize: out[n,k] = beff[k] + sum_s partial[s,n,k]
// beff computed in-block (redundantly per block; W_fc is L2-hot from main):
//   beff[k] = b_fc[k] + sum_r b_fgl[r]*W_fc[r,k], fixed-order tree.
// Then 2 outputs/thread, 128-slice sum fully unrolled (MLP>=64).
// ---------------------------------------------------------------------------
__global__ void __launch_bounds__(128)
finalize_k(const float* __restrict__ b_fgl, const float* __restrict__ W_fc,
           const float* __restrict__ b_fc, float* __restrict__ out) {
    __shared__ float red2[128][NCLS_];
    __shared__ float bsm[NCLS_];
    const int t = threadIdx.x;

    float loc[NCLS_];
#pragma unroll
    for (int k = 0; k < NCLS_; k++) loc[k] = 0.f;
#pragma unroll
    for (int it = 0; it < 16; it++) {                  // 2048 rows / 128 threads
        int r = t + it * 128;
        float bb = b_fgl[r];
        const float* wf = W_fc + r * NCLS_;
#pragma unroll
        for (int k = 0; k < NCLS_; k++) loc[k] += bb * wf[k];
    }
#pragma unroll
    for (int k = 0; k < NCLS_; k++) red2[t][k] = loc[k];
    __syncthreads();
#pragma unroll
    for (int off = 64; off >= 16; off >>= 1) {
        if (t < off) {
#pragma unroll
            for (int k = 0; k < NCLS_; k++) red2[t][k] += red2[t + off][k];
        }
        __syncthreads();
    }
    if (t < NCLS_) {
        float a0 = 0.f, a1 = 0.f;
#pragma unroll
        for (int i = 0; i < 16; i += 2) { a0 += red2[i][t]; a1 += red2[i + 1][t]; }
        bsm[t] = b_fc[t] + a0 + a1;
    }
    __syncthreads();

    int o = (blockIdx.x * 128 + t) * 2;                // 5120 outputs exactly
    int k = o % NCLS_;
    float s0 = 0.f, s1 = 0.f, u0 = 0.f, u1 = 0.f;
#pragma unroll
    for (int ss = 0; ss < SLICES; ss += 2) {
        float2 a = *(const float2*)&g_partial[(size_t)ss * (B_ * NCLS_) + o];
        float2 c = *(const float2*)&g_partial[(size_t)(ss + 1) * (B_ * NCLS_) + o];
        s0 += a.x; s1 += a.y; u0 += c.x; u1 += c.y;
    }
    *(float2*)&out[o] = make_float2(bsm[k] + s0 + u0, bsm[k + 1] + s1 + u1);
}

// ---------------------------------------------------------------------------
extern "C" void kernel_launch(void* const* d_in, const int* in_sizes, int n_in,
                              void* d_out, int out_size) {
    const float* x     = (const float*)d_in[0];   // [512, 65536]
    const float* W_fgl = (const float*)d_in[1];   // [4, 512]
    const float* b_fgl = (const float*)d_in[2];   // [4, 512]
    const float* W_fc  = (const float*)d_in[3];   // [2048, 10]
    const float* b_fc  = (const float*)d_in[4];   // [10]
    const int*   seg   = (const int*)d_in[5];     // [65536]
    float* out = (float*)d_out;                   // [512, 10]

    cudaFuncSetAttribute(fused_main_k,
                         cudaFuncAttributeMaxDynamicSharedMemorySize, SMEM_TOTAL);

    fused_main_k<<<GRIDM, 256, SMEM_TOTAL>>>(x, seg, W_fgl, W_fc);
    finalize_k<<<B_ * NCLS_ / 256, 128>>>(b_fgl, W_fc, b_fc, out);
    (void)in_sizes; (void)n_in; (void)out_size;
}

// round 9
// speedup vs baseline: 1.1655x; 1.1655x over previous
#include <cuda_runtime.h>
#include <cstdint>

// Problem constants
#define B_       512
#define P_       65536
#define NOUT_    512
#define COUT_    4
#define NCLS_    10

// Decomposition: grid 256 = 16 row-groups (g) x 16 slice-groups (sg).
// Block (g, sg) owns rows [g*32, g*32+32) and pixels [sg*4096, sg*4096+4096)
// = 32 contiguous tiles of 128 pixels. One partial write per block.
#define GRIDM    256
#define ROWS_    32
#define TILE_P   128
#define TPB      32                   // tiles per block
#define BLK_P    (TPB * TILE_P)       // 4096 pixels per block
#define XSTRIDE  132                  // smem row stride (conflict-free LDS.128)
#define WPAD     12
#define DEPTH    4                    // cp.async stages

// Dynamic smem: [xs(4) | wsm | segb(4) | red | bsm]
#define XBUF_FLOATS (ROWS_ * XSTRIDE)                  // 4224
#define XS_BYTES    (DEPTH * XBUF_FLOATS * 4)          // 67584
#define WSM_BYTES   (NOUT_ * WPAD * 4)                 // 24576
#define SEGB_BYTES  (DEPTH * TILE_P * 4)               // 2048
#define RED_BYTES   (256 * NCLS_ * 4)                  // 10240
#define BSM_BYTES   64
#define SMEM_TOTAL  (XS_BYTES + WSM_BYTES + SEGB_BYTES + RED_BYTES + BSM_BYTES)

// Scratch (allocation-free)
__device__ float g_partial[16 * B_ * NCLS_];   // [sg][512][10], 327 KB
__device__ int   g_cnt[16];                    // per-row-group arrival counters (reset each launch by last block)

__device__ __forceinline__ uint32_t smem_u32(const void* p) {
    return (uint32_t)__cvta_generic_to_shared(p);
}
__device__ __forceinline__ void cp16(void* smem, const void* gmem) {
    uint32_t a = smem_u32(smem);
    asm volatile("cp.async.cg.shared.global [%0], [%1], 16;" :: "r"(a), "l"(gmem));
}
__device__ __forceinline__ unsigned long long packf2(float v) {
    unsigned long long r;
    asm("mov.b64 %0, {%1, %1};" : "=l"(r) : "f"(v));
    return r;
}

// ---------------------------------------------------------------------------
// ONE kernel: per-block prologue builds Weff + beff; 32-tile cp.async pipeline
// accumulates acc over the whole 4096-pixel range; epilogue writes one partial;
// the last-arriving block of each row-group sums 16 partials + beff -> out.
// ---------------------------------------------------------------------------
__global__ void __launch_bounds__(256, 2)
fused_main_k(const float* __restrict__ x, const int* __restrict__ seg,
             const float* __restrict__ W_fgl, const float* __restrict__ b_fgl,
             const float* __restrict__ W_fc, const float* __restrict__ b_fc,
             float* __restrict__ out) {
    extern __shared__ __align__(16) char dynsmem[];
    float* xs   = (float*)dynsmem;                                   // [4][4224]
    float* wsm  = (float*)(dynsmem + XS_BYTES);                      // [512*12]
    int*   segb = (int*)(dynsmem + XS_BYTES + WSM_BYTES);            // [4][128]
    float* red  = (float*)(dynsmem + XS_BYTES + WSM_BYTES + SEGB_BYTES); // [2560]
    float* bsm  = (float*)(dynsmem + XS_BYTES + WSM_BYTES + SEGB_BYTES + RED_BYTES); // [10]

    const int t    = threadIdx.x;
    const int warp = t >> 5;
    const int lane = t & 31;
    const int g    = blockIdx.x >> 4;       // row-group
    const int sg   = blockIdx.x & 15;       // slice-group
    const int pBase = sg * BLK_P;

    const float* xbase = x + (size_t)(g * ROWS_) * P_ + pBase;

    auto stage = [&](int ft) {
        int buf = ft & (DEPTH - 1);
        int pOff = ft * TILE_P;
        float* xsb = xs + buf * XBUF_FLOATS;
#pragma unroll
        for (int r = 0; r < 4; r++) {
            int f   = r * 256 + t;
            int row = f >> 5;               // 32 float4 per row
            int c4  = (f & 31) << 2;
            cp16(&xsb[row * XSTRIDE + c4], xbase + (size_t)row * P_ + pOff + c4);
        }
        if (t < 32) cp16(&segb[buf * TILE_P + t * 4], seg + pBase + pOff + t * 4);
    };

    // Kick DRAM streaming first, then build Weff + beff (overlapped).
    stage(0); asm volatile("cp.async.commit_group;");
    stage(1); asm volatile("cp.async.commit_group;");
    stage(2); asm volatile("cp.async.commit_group;");

    {
        float locb[NCLS_];
#pragma unroll
        for (int k = 0; k < NCLS_; k++) locb[k] = 0.f;
#pragma unroll
        for (int jj = 0; jj < 2; jj++) {
            int j = t + jj * 256;
            float w[NCLS_];
#pragma unroll
            for (int k = 0; k < NCLS_; k++) w[k] = 0.f;
#pragma unroll
            for (int c = 0; c < COUT_; c++) {
                int r = c * NOUT_ + j;
                float a  = W_fgl[r];
                float bb = b_fgl[r];
                const float* wf = W_fc + r * NCLS_;
#pragma unroll
                for (int k = 0; k < NCLS_; k++) {
                    float wv = wf[k];
                    w[k]    += a * wv;
                    locb[k] += bb * wv;
                }
            }
#pragma unroll
            for (int k = 0; k < NCLS_; k++) wsm[j * WPAD + k] = w[k];
        }
        // beff tree: 256 partials -> bsm[10] (fixed order, deterministic)
#pragma unroll
        for (int k = 0; k < NCLS_; k++) red[t * NCLS_ + k] = locb[k];
        __syncthreads();
#pragma unroll
        for (int off = 128; off >= 16; off >>= 1) {
            if (t < off) {
#pragma unroll
                for (int k = 0; k < NCLS_; k++)
                    red[t * NCLS_ + k] += red[(t + off) * NCLS_ + k];
            }
            __syncthreads();
        }
        if (t < NCLS_) {
            float a0 = 0.f, a1 = 0.f;
#pragma unroll
            for (int i = 0; i < 16; i += 2) {
                a0 += red[i * NCLS_ + t];
                a1 += red[(i + 1) * NCLS_ + t];
            }
            bsm[t] = b_fc[t] + a0 + a1;
        }
        __syncthreads();   // bsm + wsm visible to all before main loop
    }

    unsigned long long acc[5];
#pragma unroll
    for (int q = 0; q < 5; q++) acc[q] = 0ull;

    auto compute = [&](int buf) {
        const float4* xrow =
            (const float4*)&xs[buf * XBUF_FLOATS + lane * XSTRIDE + warp * 16];
        const int4* sp = (const int4*)&segb[buf * TILE_P + warp * 16];
#pragma unroll
        for (int step = 0; step < 4; step++) {
            float4 x4  = xrow[step];     // 4 pixels of this row (LDS.128)
            int4   sid = sp[step];       // 4 seg ids (uniform -> broadcast)
#pragma unroll
            for (int j = 0; j < 4; j++) {
                int   id = (j == 0) ? sid.x : (j == 1) ? sid.y : (j == 2) ? sid.z : sid.w;
                float xv = (j == 0) ? x4.x  : (j == 1) ? x4.y  : (j == 2) ? x4.z  : x4.w;
                const unsigned long long* wrow =
                    (const unsigned long long*)&wsm[id * WPAD];
                ulonglong2 wab = *(const ulonglong2*)(wrow);      // k0..3
                ulonglong2 wcd = *(const ulonglong2*)(wrow + 2);  // k4..7
                unsigned long long we = wrow[4];                   // k8..9
                unsigned long long xp = packf2(xv);
                asm("fma.rn.f32x2 %0, %1, %2, %0;" : "+l"(acc[0]) : "l"(xp), "l"(wab.x));
                asm("fma.rn.f32x2 %0, %1, %2, %0;" : "+l"(acc[1]) : "l"(xp), "l"(wab.y));
                asm("fma.rn.f32x2 %0, %1, %2, %0;" : "+l"(acc[2]) : "l"(xp), "l"(wcd.x));
                asm("fma.rn.f32x2 %0, %1, %2, %0;" : "+l"(acc[3]) : "l"(xp), "l"(wcd.y));
                asm("fma.rn.f32x2 %0, %1, %2, %0;" : "+l"(acc[4]) : "l"(xp), "l"(we));
            }
        }
    };

#pragma unroll 1
    for (int ft = 0; ft < TPB; ft++) {
        asm volatile("cp.async.wait_group 2;");
        __syncthreads();
        if (ft + DEPTH - 1 < TPB) stage(ft + DEPTH - 1);
        asm volatile("cp.async.commit_group;");   // possibly empty: uniform count
        compute(ft & (DEPTH - 1));
    }

    // Epilogue: deterministic cross-warp reduce -> one partial per block.
#pragma unroll
    for (int q = 0; q < 5; q++) {
        float lo, hi;
        asm("mov.b64 {%0,%1}, %2;" : "=f"(lo), "=f"(hi) : "l"(acc[q]));
        red[t * NCLS_ + 2 * q]     = lo;
        red[t * NCLS_ + 2 * q + 1] = hi;
    }
    __syncthreads();
    for (int i = t; i < ROWS_ * NCLS_; i += 256) {   // 320 entries, strided
        int row = i / NCLS_;
        int k   = i - row * NCLS_;
        float sum = 0.f;
#pragma unroll
        for (int w = 0; w < 8; w++) sum += red[(w * 32 + row) * NCLS_ + k];
        g_partial[((size_t)sg * B_ + g * ROWS_ + row) * NCLS_ + k] = sum;
    }
    __syncthreads();

    // Last block of this row-group finalizes (threadFenceReduction pattern).
    __shared__ int is_last;
    if (t == 0) {
        __threadfence();
        int old = atomicAdd(&g_cnt[g], 1);
        is_last = (old == 15);
    }
    __syncthreads();
    if (is_last) {
        __threadfence();   // acquire all 16 partials
        for (int i = t; i < ROWS_ * NCLS_; i += 256) {
            int row = i / NCLS_;
            int k   = i - row * NCLS_;
            int n   = g * ROWS_ + row;
            float sum = bsm[k];
#pragma unroll
            for (int s = 0; s < 16; s++)     // fixed order: deterministic
                sum += g_partial[((size_t)s * B_ + n) * NCLS_ + k];
            out[n * NCLS_ + k] = sum;
        }
        __syncthreads();
        if (t == 0) g_cnt[g] = 0;            // reset for next (graph) launch
    }
}

// ---------------------------------------------------------------------------
extern "C" void kernel_launch(void* const* d_in, const int* in_sizes, int n_in,
                              void* d_out, int out_size) {
    const float* x     = (const float*)d_in[0];   // [512, 65536]
    const float* W_fgl = (const float*)d_in[1];   // [4, 512]
    const float* b_fgl = (const float*)d_in[2];   // [4, 512]
    const float* W_fc  = (const float*)d_in[3];   // [2048, 10]
    const float* b_fc  = (const float*)d_in[4];   // [10]
    const int*   seg   = (const int*)d_in[5];     // [65536]
    float* out = (float*)d_out;                   // [512, 10]

    cudaFuncSetAttribute(fused_main_k,
                         cudaFuncAttributeMaxDynamicSharedMemorySize, SMEM_TOTAL);

    fused_main_k<<<GRIDM, 256, SMEM_TOTAL>>>(x, seg, W_fgl, b_fgl, W_fc, b_fc, out);
    (void)in_sizes; (void)n_in; (void)out_size;
}

// round 10
// speedup vs baseline: 1.4105x; 1.2102x over previous
#include <cuda_runtime.h>
#include <cstdint>

// Problem constants
#define B_       512
#define P_       65536
#define NOUT_    512
#define COUT_    4
#define NCLS_    10

// Decomposition: grid 256 = 8 row-groups (64 rows) x 32 px-groups (2048 px).
// Block: 512 threads (16 warps). Tile = 64 px; 32 tiles per block.
// Each lane covers TWO rows (lane, lane+32): one weight broadcast feeds both.
#define GRIDM    256
#define ROWS_    64
#define TILE_P   64
#define TPB      32                    // tiles per block
#define BLK_P    (TPB * TILE_P)        // 2048 px per block
#define XSTR     68                    // 68 mod 32 == 4 -> conflict-free LDS.128 phases
#define WPAD     12
#define DEPTH    4
#define NSG      32                    // px-groups (partials per row-group)

#define XBUF_FLOATS (ROWS_ * XSTR)                     // 4352
#define XS_BYTES    (DEPTH * XBUF_FLOATS * 4)          // 69632
#define WSM_BYTES   (NOUT_ * WPAD * 4)                 // 24576
#define SEGB_BYTES  (DEPTH * TILE_P * 4)               // 1024
#define BSM_BYTES   (16 * NCLS_ * 4 + 64)              // warp partials + bsm
#define SMEM_TOTAL  (XS_BYTES + WSM_BYTES + SEGB_BYTES + BSM_BYTES)  // ~95.9KB -> 2 blocks/SM

// Scratch (allocation-free)
__device__ float g_partial[NSG * B_ * NCLS_];   // [32][512][10], 655KB
__device__ int   g_cnt[8];                      // per-row-group arrival counters

__device__ __forceinline__ uint32_t smem_u32(const void* p) {
    return (uint32_t)__cvta_generic_to_shared(p);
}
__device__ __forceinline__ void cp16(void* smem, const void* gmem) {
    uint32_t a = smem_u32(smem);
    asm volatile("cp.async.cg.shared.global [%0], [%1], 16;" :: "r"(a), "l"(gmem));
}
__device__ __forceinline__ unsigned long long packf2(float v) {
    unsigned long long r;
    asm("mov.b64 %0, {%1, %1};" : "=l"(r) : "f"(v));
    return r;
}

// ---------------------------------------------------------------------------
// ONE kernel. Prologue: stage tiles 0..2, build Weff (smem) + beff (shfl tree).
// Main loop: 4-deep cp.async pipeline; per pixel ONE weight fetch -> FMAs for
// TWO rows. Epilogue: block partial -> g_partial; last block per row-group
// sums 32 partials + beff -> out (threadFenceReduction pattern, fixed order).
// ---------------------------------------------------------------------------
__global__ void __launch_bounds__(512, 2)
fused_main_k(const float* __restrict__ x, const int* __restrict__ seg,
             const float* __restrict__ W_fgl, const float* __restrict__ b_fgl,
             const float* __restrict__ W_fc, const float* __restrict__ b_fc,
             float* __restrict__ out) {
    extern __shared__ __align__(16) char dynsmem[];
    float* xs   = (float*)dynsmem;                                    // [4][4352]
    float* wsm  = (float*)(dynsmem + XS_BYTES);                       // [512*12]
    int*   segb = (int*)(dynsmem + XS_BYTES + WSM_BYTES);             // [4][64]
    float* bred = (float*)(dynsmem + XS_BYTES + WSM_BYTES + SEGB_BYTES); // [16][10]
    float* bsm  = bred + 16 * NCLS_;                                  // [10]

    const int t    = threadIdx.x;
    const int warp = t >> 5;
    const int lane = t & 31;
    const int g    = blockIdx.x >> 5;       // row-group (0..7)
    const int sg   = blockIdx.x & 31;       // px-group  (0..31)
    const int pBase = sg * BLK_P;

    const float* xbase = x + (size_t)(g * ROWS_) * P_ + pBase;

    auto stage = [&](int ft) {
        int buf  = ft & (DEPTH - 1);
        int pOff = ft * TILE_P;
        float* xsb = xs + buf * XBUF_FLOATS;
#pragma unroll
        for (int r = 0; r < 2; r++) {          // 1024 float4 over 512 threads
            int f   = r * 512 + t;
            int row = f >> 4;                  // 16 float4 per row
            int c4  = (f & 15) << 2;
            cp16(&xsb[row * XSTR + c4], xbase + (size_t)row * P_ + pOff + c4);
        }
        if (t < 16) cp16(&segb[buf * TILE_P + t * 4], seg + pBase + pOff + t * 4);
    };

    // Kick DRAM streaming first, then build Weff + beff (overlapped with TMA... cp.async).
    stage(0); asm volatile("cp.async.commit_group;");
    stage(1); asm volatile("cp.async.commit_group;");
    stage(2); asm volatile("cp.async.commit_group;");

    {
        int j = t;                              // 512 threads == 512 regions
        float w[NCLS_], locb[NCLS_];
#pragma unroll
        for (int k = 0; k < NCLS_; k++) { w[k] = 0.f; locb[k] = 0.f; }
#pragma unroll
        for (int c = 0; c < COUT_; c++) {
            int r = c * NOUT_ + j;
            float a  = W_fgl[r];
            float bb = b_fgl[r];
            const float* wf = W_fc + r * NCLS_;
#pragma unroll
            for (int k = 0; k < NCLS_; k++) {
                float wv = wf[k];
                w[k]    += a * wv;
                locb[k] += bb * wv;
            }
        }
#pragma unroll
        for (int k = 0; k < NCLS_; k++) wsm[j * WPAD + k] = w[k];
        // beff: warp shfl tree (fixed order) -> 16 warp partials -> bsm
#pragma unroll
        for (int off = 16; off >= 1; off >>= 1)
#pragma unroll
            for (int k = 0; k < NCLS_; k++)
                locb[k] += __shfl_xor_sync(0xffffffffu, locb[k], off);
        if (lane == 0)
#pragma unroll
            for (int k = 0; k < NCLS_; k++) bred[warp * NCLS_ + k] = locb[k];
    }
    // (loop iteration 0's __syncthreads orders wsm/bred STS before any reads)

    unsigned long long accA[5], accB[5];        // f32x2 per class pair, 2 rows
#pragma unroll
    for (int q = 0; q < 5; q++) { accA[q] = 0ull; accB[q] = 0ull; }

    auto compute = [&](int buf) {
        // warp handles px [warp*4, warp*4+4); lane handles rows lane, lane+32
        const float* xb = &xs[buf * XBUF_FLOATS + lane * XSTR + warp * 4];
        float4 xa = *(const float4*)xb;                       // row = lane
        float4 xc = *(const float4*)(xb + 32 * XSTR);         // row = lane+32
        int4 sid = *(const int4*)&segb[buf * TILE_P + warp * 4];  // broadcast
#pragma unroll
        for (int j = 0; j < 4; j++) {
            int   id  = (j == 0) ? sid.x : (j == 1) ? sid.y : (j == 2) ? sid.z : sid.w;
            float xv0 = (j == 0) ? xa.x  : (j == 1) ? xa.y  : (j == 2) ? xa.z  : xa.w;
            float xv1 = (j == 0) ? xc.x  : (j == 1) ? xc.y  : (j == 2) ? xc.z  : xc.w;
            const unsigned long long* wrow = (const unsigned long long*)&wsm[id * WPAD];
            ulonglong2 wab = *(const ulonglong2*)(wrow);      // k0..3  (broadcast)
            ulonglong2 wcd = *(const ulonglong2*)(wrow + 2);  // k4..7
            unsigned long long we = wrow[4];                   // k8..9
            unsigned long long xp0 = packf2(xv0);
            unsigned long long xp1 = packf2(xv1);
            asm("fma.rn.f32x2 %0, %1, %2, %0;" : "+l"(accA[0]) : "l"(xp0), "l"(wab.x));
            asm("fma.rn.f32x2 %0, %1, %2, %0;" : "+l"(accB[0]) : "l"(xp1), "l"(wab.x));
            asm("fma.rn.f32x2 %0, %1, %2, %0;" : "+l"(accA[1]) : "l"(xp0), "l"(wab.y));
            asm("fma.rn.f32x2 %0, %1, %2, %0;" : "+l"(accB[1]) : "l"(xp1), "l"(wab.y));
            asm("fma.rn.f32x2 %0, %1, %2, %0;" : "+l"(accA[2]) : "l"(xp0), "l"(wcd.x));
            asm("fma.rn.f32x2 %0, %1, %2, %0;" : "+l"(accB[2]) : "l"(xp1), "l"(wcd.x));
            asm("fma.rn.f32x2 %0, %1, %2, %0;" : "+l"(accA[3]) : "l"(xp0), "l"(wcd.y));
            asm("fma.rn.f32x2 %0, %1, %2, %0;" : "+l"(accB[3]) : "l"(xp1), "l"(wcd.y));
            asm("fma.rn.f32x2 %0, %1, %2, %0;" : "+l"(accA[4]) : "l"(xp0), "l"(we));
            asm("fma.rn.f32x2 %0, %1, %2, %0;" : "+l"(accB[4]) : "l"(xp1), "l"(we));
        }
    };

#pragma unroll 1
    for (int ft = 0; ft < TPB; ft++) {
        asm volatile("cp.async.wait_group 2;");
        __syncthreads();
        if (ft + DEPTH - 1 < TPB) stage(ft + DEPTH - 1);
        asm volatile("cp.async.commit_group;");   // possibly empty: uniform count
        compute(ft & (DEPTH - 1));
    }
    __syncthreads();   // all computes done before xs is reused as reduction space

    // Epilogue: per-warp partials (16 warps x 64 rows x 10) into xs, fixed order.
    float* red = xs;   // 10240 floats needed <= 17408 (4 buffers available)
#pragma unroll
    for (int q = 0; q < 5; q++) {
        float lo, hi;
        asm("mov.b64 {%0,%1}, %2;" : "=f"(lo), "=f"(hi) : "l"(accA[q]));
        red[(warp * ROWS_ + lane) * NCLS_ + 2 * q]     = lo;
        red[(warp * ROWS_ + lane) * NCLS_ + 2 * q + 1] = hi;
        asm("mov.b64 {%0,%1}, %2;" : "=f"(lo), "=f"(hi) : "l"(accB[q]));
        red[(warp * ROWS_ + lane + 32) * NCLS_ + 2 * q]     = lo;
        red[(warp * ROWS_ + lane + 32) * NCLS_ + 2 * q + 1] = hi;
    }
    __syncthreads();
    // bsm final (10 threads): 16 warp partials + b_fc, fixed order
    if (t < NCLS_) {
        float a0 = 0.f, a1 = 0.f;
#pragma unroll
        for (int i = 0; i < 16; i += 2) {
            a0 += bred[i * NCLS_ + t];
            a1 += bred[(i + 1) * NCLS_ + t];
        }
        bsm[t] = b_fc[t] + a0 + a1;
    }
    for (int i = t; i < ROWS_ * NCLS_; i += 512) {   // 640 entries
        int row = i / NCLS_;
        int k   = i - row * NCLS_;
        float sum = 0.f;
#pragma unroll
        for (int w = 0; w < 16; w++) sum += red[(w * ROWS_ + row) * NCLS_ + k];
        g_partial[((size_t)sg * B_ + g * ROWS_ + row) * NCLS_ + k] = sum;
    }
    __syncthreads();

    // Last block of this row-group finalizes.
    __shared__ int is_last;
    if (t == 0) {
        __threadfence();
        int old = atomicAdd(&g_cnt[g], 1);
        is_last = (old == NSG - 1);
    }
    __syncthreads();
    if (is_last) {
        __threadfence();   // acquire all 32 partials
        for (int i = t; i < ROWS_ * NCLS_; i += 512) {
            int row = i / NCLS_;
            int k   = i - row * NCLS_;
            int n   = g * ROWS_ + row;
            float sum = bsm[k];
#pragma unroll
            for (int s = 0; s < NSG; s++)      // fixed order: deterministic
                sum += g_partial[((size_t)s * B_ + n) * NCLS_ + k];
            out[n * NCLS_ + k] = sum;
        }
        __syncthreads();
        if (t == 0) g_cnt[g] = 0;              // reset for next (graph) launch
    }
}

// ---------------------------------------------------------------------------
extern "C" void kernel_launch(void* const* d_in, const int* in_sizes, int n_in,
                              void* d_out, int out_size) {
    const float* x     = (const float*)d_in[0];   // [512, 65536]
    const float* W_fgl = (const float*)d_in[1];   // [4, 512]
    const float* b_fgl = (const float*)d_in[2];   // [4, 512]
    const float* W_fc  = (const float*)d_in[3];   // [2048, 10]
    const float* b_fc  = (const float*)d_in[4];   // [10]
    const int*   seg   = (const int*)d_in[5];     // [65536]
    float* out = (float*)d_out;                   // [512, 10]

    cudaFuncSetAttribute(fused_main_k,
                         cudaFuncAttributeMaxDynamicSharedMemorySize, SMEM_TOTAL);

    fused_main_k<<<GRIDM, 512, SMEM_TOTAL>>>(x, seg, W_fgl, b_fgl, W_fc, b_fc, out);
    (void)in_sizes; (void)n_in; (void)out_size;
}

// round 11
// speedup vs baseline: 1.4733x; 1.0445x over previous
#include <cuda_runtime.h>
#include <cstdint>

// Problem constants
#define B_       512
#define P_       65536
#define NOUT_    512
#define COUT_    4
#define NCLS_    10

// Decomposition: grid 148 = 4 row-groups (128 rows) x 37 px-groups.
// 1 block/SM (512 threads, 128 regs). Tile = 64 px; each rg has 1024 tiles;
// px-group pg owns contiguous tiles [pg*1024/37, (pg+1)*1024/37) -> 27 or 28.
// Lane covers FOUR rows (lane, +32, +64, +96): one weight broadcast -> 20 FFMA2.
#define RGS      4
#define RROWS    128
#define PGS      37
#define GRIDM    (RGS * PGS)          // 148
#define TILE_P   64
#define TILES_RG 1024
#define XSTR     68                   // floats per row in smem (pad 4: conflict-free LDS.128)
#define WPAD     12
#define DEPTH    5

#define XBUF_FLOATS (RROWS * XSTR)                     // 8704
#define XS_BYTES    (DEPTH * XBUF_FLOATS * 4)          // 174080
#define WSM_BYTES   (NOUT_ * WPAD * 4)                 // 24576
#define SEGB_BYTES  (DEPTH * TILE_P * 4)               // 1280
#define BRED_BYTES  (16 * NCLS_ * 4 + 64)              // warp beff partials + bsm
#define SMEM_TOTAL  (XS_BYTES + WSM_BYTES + SEGB_BYTES + BRED_BYTES)  // 200640

// Scratch (allocation-free)
__device__ float g_partial[PGS * B_ * NCLS_];   // [37][512][10], 758KB
__device__ int   g_cnt[RGS];                    // arrival counters (reset by finalizer)

__device__ __forceinline__ uint32_t smem_u32(const void* p) {
    return (uint32_t)__cvta_generic_to_shared(p);
}
__device__ __forceinline__ void cp16(void* smem, const void* gmem) {
    uint32_t a = smem_u32(smem);
    asm volatile("cp.async.cg.shared.global [%0], [%1], 16;" :: "r"(a), "l"(gmem));
}
__device__ __forceinline__ unsigned long long packf2(float v) {
    unsigned long long r;
    asm("mov.b64 %0, {%1, %1};" : "=l"(r) : "f"(v));
    return r;
}
#define FMA2(acc, xv, wv) \
    asm("fma.rn.f32x2 %0, %1, %2, %0;" : "+l"(acc) : "l"(xv), "l"(wv))

// ---------------------------------------------------------------------------
__global__ void __launch_bounds__(512, 1)
fused_main_k(const float* __restrict__ x, const int* __restrict__ seg,
             const float* __restrict__ W_fgl, const float* __restrict__ b_fgl,
             const float* __restrict__ W_fc, const float* __restrict__ b_fc,
             float* __restrict__ out) {
    extern __shared__ __align__(16) char dynsmem[];
    float* xs   = (float*)dynsmem;                                    // [5][8704]
    float* wsm  = (float*)(dynsmem + XS_BYTES);                       // [512*12]
    int*   segb = (int*)(dynsmem + XS_BYTES + WSM_BYTES);             // [5][64]
    float* bred = (float*)(dynsmem + XS_BYTES + WSM_BYTES + SEGB_BYTES); // [16][10]
    float* bsm  = bred + 16 * NCLS_;                                  // [10]

    const int t    = threadIdx.x;
    const int warp = t >> 5;
    const int lane = t & 31;
    const int g    = blockIdx.x / PGS;      // row-group (0..3)
    const int pg   = blockIdx.x % PGS;      // px-group  (0..36)
    const int tStart = (pg * TILES_RG) / PGS;
    const int nT     = ((pg + 1) * TILES_RG) / PGS - tStart;   // 27 or 28

    const float* xbase = x + (size_t)(g * RROWS) * P_;

    auto stage = [&](int ft) {
        int buf  = ft % DEPTH;
        int pOff = (tStart + ft) * TILE_P;
        float* xsb = xs + buf * XBUF_FLOATS;
#pragma unroll
        for (int r = 0; r < 4; r++) {          // 2048 float4 over 512 threads
            int f   = r * 512 + t;
            int row = f >> 4;                  // 16 float4 per row
            int c4  = (f & 15) << 2;
            cp16(&xsb[row * XSTR + c4], xbase + (size_t)row * P_ + pOff + c4);
        }
        if (t < 16) cp16(&segb[buf * TILE_P + t * 4], seg + pOff + t * 4);
    };

    // Prologue: 4 tile groups in flight, then build Weff + beff (overlapped).
    stage(0); asm volatile("cp.async.commit_group;");
    stage(1); asm volatile("cp.async.commit_group;");
    stage(2); asm volatile("cp.async.commit_group;");
    stage(3); asm volatile("cp.async.commit_group;");

    {
        int j = t;                              // 512 threads == 512 regions
        float w[NCLS_], locb[NCLS_];
#pragma unroll
        for (int k = 0; k < NCLS_; k++) { w[k] = 0.f; locb[k] = 0.f; }
#pragma unroll
        for (int c = 0; c < COUT_; c++) {
            int r = c * NOUT_ + j;
            float a  = W_fgl[r];
            float bb = b_fgl[r];
            const float* wf = W_fc + r * NCLS_;
#pragma unroll
            for (int k = 0; k < NCLS_; k++) {
                float wv = wf[k];
                w[k]    += a * wv;
                locb[k] += bb * wv;
            }
        }
#pragma unroll
        for (int k = 0; k < NCLS_; k++) wsm[j * WPAD + k] = w[k];
#pragma unroll
        for (int off = 16; off >= 1; off >>= 1)
#pragma unroll
            for (int k = 0; k < NCLS_; k++)
                locb[k] += __shfl_xor_sync(0xffffffffu, locb[k], off);
        if (lane == 0)
#pragma unroll
            for (int k = 0; k < NCLS_; k++) bred[warp * NCLS_ + k] = locb[k];
    }
    // (first loop iteration's __syncthreads orders wsm/bred before reads)

    unsigned long long acc[4][5];   // [row-set][class-pair] f32x2
#pragma unroll
    for (int rs = 0; rs < 4; rs++)
#pragma unroll
        for (int q = 0; q < 5; q++) acc[rs][q] = 0ull;

    auto compute = [&](int buf) {
        const float* xb = &xs[buf * XBUF_FLOATS + lane * XSTR + warp * 4];
        float4 xr[4];
        xr[0] = *(const float4*)(xb);                 // row = lane
        xr[1] = *(const float4*)(xb + 32 * XSTR);     // row = lane+32
        xr[2] = *(const float4*)(xb + 64 * XSTR);     // row = lane+64
        xr[3] = *(const float4*)(xb + 96 * XSTR);     // row = lane+96
        int4 sid = *(const int4*)&segb[buf * TILE_P + warp * 4];  // broadcast
#pragma unroll
        for (int j = 0; j < 4; j++) {
            int id = (j == 0) ? sid.x : (j == 1) ? sid.y : (j == 2) ? sid.z : sid.w;
            const unsigned long long* wrow = (const unsigned long long*)&wsm[id * WPAD];
            ulonglong2 wab = *(const ulonglong2*)(wrow);      // k0..3  (broadcast)
            ulonglong2 wcd = *(const ulonglong2*)(wrow + 2);  // k4..7
            unsigned long long we = wrow[4];                   // k8..9
#pragma unroll
            for (int rs = 0; rs < 4; rs++) {
                float xv = (j == 0) ? xr[rs].x : (j == 1) ? xr[rs].y
                         : (j == 2) ? xr[rs].z : xr[rs].w;
                unsigned long long xp = packf2(xv);
                FMA2(acc[rs][0], xp, wab.x);
                FMA2(acc[rs][1], xp, wab.y);
                FMA2(acc[rs][2], xp, wcd.x);
                FMA2(acc[rs][3], xp, wcd.y);
                FMA2(acc[rs][4], xp, we);
            }
        }
    };

#pragma unroll 1
    for (int ft = 0; ft < nT; ft++) {
        asm volatile("cp.async.wait_group 3;");
        __syncthreads();
        if (ft + DEPTH - 1 < nT) stage(ft + DEPTH - 1);   // -> buf (ft-1)%5, safe
        asm volatile("cp.async.commit_group;");            // empty at tail: uniform
        compute(ft % DEPTH);
    }
    __syncthreads();   // all computes done; xs reusable as reduction space

    // Epilogue: reduce 16 warps' partials -> one block partial (fixed order).
    // red layout: [8 warp-slots][128 rows][10]; warps 8..15 fold into slots 0..7.
    float* red = xs;                                       // 10240 floats used
#pragma unroll
    for (int rs = 0; rs < 4; rs++) {
        int row = lane + rs * 32;
        if (warp < 8) {
#pragma unroll
            for (int q = 0; q < 5; q++) {
                float lo, hi;
                asm("mov.b64 {%0,%1}, %2;" : "=f"(lo), "=f"(hi) : "l"(acc[rs][q]));
                red[(warp * RROWS + row) * NCLS_ + 2 * q]     = lo;
                red[(warp * RROWS + row) * NCLS_ + 2 * q + 1] = hi;
            }
        }
    }
    __syncthreads();
    if (warp >= 8) {
#pragma unroll
        for (int rs = 0; rs < 4; rs++) {
            int row = lane + rs * 32;
            float* dst = &red[((warp - 8) * RROWS + row) * NCLS_];
#pragma unroll
            for (int q = 0; q < 5; q++) {
                float lo, hi;
                asm("mov.b64 {%0,%1}, %2;" : "=f"(lo), "=f"(hi) : "l"(acc[rs][q]));
                dst[2 * q]     += lo;
                dst[2 * q + 1] += hi;
            }
        }
    }
    __syncthreads();
#pragma unroll
    for (int off = 4; off >= 1; off >>= 1) {
        for (int i = t; i < off * RROWS * NCLS_; i += 512) {
            int slot = i / (RROWS * NCLS_);
            int rem  = i - slot * (RROWS * NCLS_);
            red[slot * RROWS * NCLS_ + rem] += red[(slot + off) * RROWS * NCLS_ + rem];
        }
        __syncthreads();
    }
    // bsm: 16 warp beff partials + b_fc (fixed order)
    if (t < NCLS_) {
        float a0 = 0.f, a1 = 0.f;
#pragma unroll
        for (int i = 0; i < 16; i += 2) {
            a0 += bred[i * NCLS_ + t];
            a1 += bred[(i + 1) * NCLS_ + t];
        }
        bsm[t] = b_fc[t] + a0 + a1;
    }
    for (int i = t; i < RROWS * NCLS_; i += 512) {   // 1280 entries
        g_partial[((size_t)pg * B_ + g * RROWS) * NCLS_ + i] = red[i];
    }
    __syncthreads();

    // Last block of this row-group finalizes (threadFenceReduction pattern).
    __shared__ int is_last;
    if (t == 0) {
        __threadfence();
        int old = atomicAdd(&g_cnt[g], 1);
        is_last = (old == PGS - 1);
    }
    __syncthreads();
    if (is_last) {
        __threadfence();   // acquire all 37 partials
        for (int i = t; i < RROWS * NCLS_; i += 512) {
            int n = g * RROWS + i / NCLS_;
            int k = i % NCLS_;
            float sum = bsm[k];
#pragma unroll
            for (int s = 0; s < PGS; s++)      // fixed order: deterministic
                sum += g_partial[((size_t)s * B_ + n) * NCLS_ + k];
            out[n * NCLS_ + k] = sum;
        }
        __syncthreads();
        if (t == 0) g_cnt[g] = 0;              // reset for next (graph) launch
    }
}

// ---------------------------------------------------------------------------
extern "C" void kernel_launch(void* const* d_in, const int* in_sizes, int n_in,
                              void* d_out, int out_size) {
    const float* x     = (const float*)d_in[0];   // [512, 65536]
    const float* W_fgl = (const float*)d_in[1];   // [4, 512]
    const float* b_fgl = (const float*)d_in[2];   // [4, 512]
    const float* W_fc  = (const float*)d_in[3];   // [2048, 10]
    const float* b_fc  = (const float*)d_in[4];   // [10]
    const int*   seg   = (const int*)d_in[5];     // [65536]
    float* out = (float*)d_out;                   // [512, 10]

    cudaFuncSetAttribute(fused_main_k,
                         cudaFuncAttributeMaxDynamicSharedMemorySize, SMEM_TOTAL);

    fused_main_k<<<GRIDM, 512, SMEM_TOTAL>>>(x, seg, W_fgl, b_fgl, W_fc, b_fc, out);
    (void)in_sizes; (void)n_in; (void)out_size;
}

// round 12
// speedup vs baseline: 1.4777x; 1.0030x over previous
#include <cuda_runtime.h>
#include <cstdint>

// Problem constants
#define B_       512
#define P_       65536
#define NOUT_    512
#define COUT_    4
#define NCLS_    10

// Decomposition: grid 148 = 4 row-groups (128 rows) x 37 px-groups.
// 1 block/SM (512 threads). Tile = 128 px (512 B contiguous per row -> better
// DRAM page locality than R11's 256 B); each rg has 512 tiles; px-group pg owns
// contiguous tiles [pg*512/37, (pg+1)*512/37) -> 13 or 14.
// Lane covers FOUR rows (lane, +32, +64, +96): one weight broadcast -> 20 FFMA2.
#define RGS      4
#define RROWS    128
#define PGS      37
#define GRIDM    (RGS * PGS)          // 148
#define TILE_P   128
#define TILES_RG 512
#define XSTR     132                  // floats per smem row (pad 4: conflict-free LDS.128)
#define WPAD     12
#define DEPTH    3

#define XBUF_FLOATS (RROWS * XSTR)                     // 16896
#define XS_BYTES    (DEPTH * XBUF_FLOATS * 4)          // 202752
#define WSM_BYTES   (NOUT_ * WPAD * 4)                 // 24576
#define SEGB_BYTES  (DEPTH * TILE_P * 4)               // 1536
#define BRED_BYTES  (16 * NCLS_ * 4 + 64)              // 704
#define SMEM_TOTAL  (XS_BYTES + WSM_BYTES + SEGB_BYTES + BRED_BYTES)  // 229568 <= 232448

// Scratch (allocation-free)
__device__ float g_partial[PGS * B_ * NCLS_];   // [37][512][10]
__device__ int   g_cnt[RGS];                    // arrival counters (reset by finalizer)

__device__ __forceinline__ uint32_t smem_u32(const void* p) {
    return (uint32_t)__cvta_generic_to_shared(p);
}
__device__ __forceinline__ void cp16(void* smem, const void* gmem) {
    uint32_t a = smem_u32(smem);
    asm volatile("cp.async.cg.shared.global [%0], [%1], 16;" :: "r"(a), "l"(gmem));
}
__device__ __forceinline__ unsigned long long packf2(float v) {
    unsigned long long r;
    asm("mov.b64 %0, {%1, %1};" : "=l"(r) : "f"(v));
    return r;
}
#define FMA2(acc, xv, wv) \
    asm("fma.rn.f32x2 %0, %1, %2, %0;" : "+l"(acc) : "l"(xv), "l"(wv))

// ---------------------------------------------------------------------------
__global__ void __launch_bounds__(512, 1)
fused_main_k(const float* __restrict__ x, const int* __restrict__ seg,
             const float* __restrict__ W_fgl, const float* __restrict__ b_fgl,
             const float* __restrict__ W_fc, const float* __restrict__ b_fc,
             float* __restrict__ out) {
    extern __shared__ __align__(16) char dynsmem[];
    float* xs   = (float*)dynsmem;                                    // [3][16896]
    float* wsm  = (float*)(dynsmem + XS_BYTES);                       // [512*12]
    int*   segb = (int*)(dynsmem + XS_BYTES + WSM_BYTES);             // [3][128]
    float* bred = (float*)(dynsmem + XS_BYTES + WSM_BYTES + SEGB_BYTES); // [16][10]
    float* bsm  = bred + 16 * NCLS_;                                  // [10]

    const int t    = threadIdx.x;
    const int warp = t >> 5;
    const int lane = t & 31;
    const int g    = blockIdx.x / PGS;      // row-group (0..3)
    const int pg   = blockIdx.x % PGS;      // px-group  (0..36)
    const int tStart = (pg * TILES_RG) / PGS;
    const int nT     = ((pg + 1) * TILES_RG) / PGS - tStart;   // 13 or 14

    const float* xbase = x + (size_t)(g * RROWS) * P_;

    auto stage = [&](int ft) {
        int buf  = ft % DEPTH;
        int pOff = (tStart + ft) * TILE_P;
        float* xsb = xs + buf * XBUF_FLOATS;
#pragma unroll
        for (int r = 0; r < 8; r++) {          // 4096 float4 over 512 threads
            int f   = r * 512 + t;
            int row = f >> 5;                  // 32 float4 per row
            int c4  = (f & 31) << 2;
            cp16(&xsb[row * XSTR + c4], xbase + (size_t)row * P_ + pOff + c4);
        }
        if (t < 32) cp16(&segb[buf * TILE_P + t * 4], seg + pOff + t * 4);
    };

    // Prologue: 2 tiles in flight, then build Weff + beff (overlapped).
    stage(0); asm volatile("cp.async.commit_group;");
    stage(1); asm volatile("cp.async.commit_group;");

    {
        int j = t;                              // 512 threads == 512 regions
        float w[NCLS_], locb[NCLS_];
#pragma unroll
        for (int k = 0; k < NCLS_; k++) { w[k] = 0.f; locb[k] = 0.f; }
#pragma unroll
        for (int c = 0; c < COUT_; c++) {
            int r = c * NOUT_ + j;
            float a  = W_fgl[r];
            float bb = b_fgl[r];
            const float* wf = W_fc + r * NCLS_;
#pragma unroll
            for (int k = 0; k < NCLS_; k++) {
                float wv = wf[k];
                w[k]    += a * wv;
                locb[k] += bb * wv;
            }
        }
#pragma unroll
        for (int k = 0; k < NCLS_; k++) wsm[j * WPAD + k] = w[k];
#pragma unroll
        for (int off = 16; off >= 1; off >>= 1)
#pragma unroll
            for (int k = 0; k < NCLS_; k++)
                locb[k] += __shfl_xor_sync(0xffffffffu, locb[k], off);
        if (lane == 0)
#pragma unroll
            for (int k = 0; k < NCLS_; k++) bred[warp * NCLS_ + k] = locb[k];
    }
    // (first loop iteration's __syncthreads orders wsm/bred before reads)

    unsigned long long acc[4][5];   // [row-set][class-pair] f32x2
#pragma unroll
    for (int rs = 0; rs < 4; rs++)
#pragma unroll
        for (int q = 0; q < 5; q++) acc[rs][q] = 0ull;

    auto compute = [&](int buf) {
        // warp handles px [warp*8, warp*8+8); lane rows: lane,+32,+64,+96
        const float* xb = &xs[buf * XBUF_FLOATS + lane * XSTR + warp * 8];
        int4 s0 = *(const int4*)&segb[buf * TILE_P + warp * 8];       // broadcast
        int4 s1 = *(const int4*)&segb[buf * TILE_P + warp * 8 + 4];
#pragma unroll
        for (int h = 0; h < 2; h++) {
            float4 xr[4];
#pragma unroll
            for (int rs = 0; rs < 4; rs++)
                xr[rs] = *(const float4*)(xb + rs * 32 * XSTR + h * 4);
            int4 sid = h ? s1 : s0;
#pragma unroll
            for (int j = 0; j < 4; j++) {
                int id = (j == 0) ? sid.x : (j == 1) ? sid.y : (j == 2) ? sid.z : sid.w;
                const unsigned long long* wrow =
                    (const unsigned long long*)&wsm[id * WPAD];
                ulonglong2 wab = *(const ulonglong2*)(wrow);      // k0..3 (broadcast)
                ulonglong2 wcd = *(const ulonglong2*)(wrow + 2);  // k4..7
                unsigned long long we = wrow[4];                   // k8..9
#pragma unroll
                for (int rs = 0; rs < 4; rs++) {
                    float xv = (j == 0) ? xr[rs].x : (j == 1) ? xr[rs].y
                             : (j == 2) ? xr[rs].z : xr[rs].w;
                    unsigned long long xp = packf2(xv);
                    FMA2(acc[rs][0], xp, wab.x);
                    FMA2(acc[rs][1], xp, wab.y);
                    FMA2(acc[rs][2], xp, wcd.x);
                    FMA2(acc[rs][3], xp, wcd.y);
                    FMA2(acc[rs][4], xp, we);
                }
            }
        }
    };

#pragma unroll 1
    for (int ft = 0; ft < nT; ft++) {
        asm volatile("cp.async.wait_group 1;");
        __syncthreads();
        if (ft + DEPTH - 1 < nT) stage(ft + DEPTH - 1);   // -> buf (ft-1)%3, safe
        asm volatile("cp.async.commit_group;");            // empty at tail: uniform
        compute(ft % DEPTH);
    }
    __syncthreads();   // all computes done; xs reusable as reduction space

    // Epilogue: reduce 16 warps' partials -> one block partial (fixed order).
    // red layout: [8 warp-slots][128 rows][10]; warps 8..15 fold into slots 0..7.
    float* red = xs;                                       // 10240 floats used
#pragma unroll
    for (int rs = 0; rs < 4; rs++) {
        int row = lane + rs * 32;
        if (warp < 8) {
#pragma unroll
            for (int q = 0; q < 5; q++) {
                float lo, hi;
                asm("mov.b64 {%0,%1}, %2;" : "=f"(lo), "=f"(hi) : "l"(acc[rs][q]));
                red[(warp * RROWS + row) * NCLS_ + 2 * q]     = lo;
                red[(warp * RROWS + row) * NCLS_ + 2 * q + 1] = hi;
            }
        }
    }
    __syncthreads();
    if (warp >= 8) {
#pragma unroll
        for (int rs = 0; rs < 4; rs++) {
            int row = lane + rs * 32;
            float* dst = &red[((warp - 8) * RROWS + row) * NCLS_];
#pragma unroll
            for (int q = 0; q < 5; q++) {
                float lo, hi;
                asm("mov.b64 {%0,%1}, %2;" : "=f"(lo), "=f"(hi) : "l"(acc[rs][q]));
                dst[2 * q]     += lo;
                dst[2 * q + 1] += hi;
            }
        }
    }
    __syncthreads();
#pragma unroll
    for (int off = 4; off >= 1; off >>= 1) {
        for (int i = t; i < off * RROWS * NCLS_; i += 512) {
            int slot = i / (RROWS * NCLS_);
            int rem  = i - slot * (RROWS * NCLS_);
            red[slot * RROWS * NCLS_ + rem] += red[(slot + off) * RROWS * NCLS_ + rem];
        }
        __syncthreads();
    }
    // bsm: 16 warp beff partials + b_fc (fixed order)
    if (t < NCLS_) {
        float a0 = 0.f, a1 = 0.f;
#pragma unroll
        for (int i = 0; i < 16; i += 2) {
            a0 += bred[i * NCLS_ + t];
            a1 += bred[(i + 1) * NCLS_ + t];
        }
        bsm[t] = b_fc[t] + a0 + a1;
    }
    for (int i = t; i < RROWS * NCLS_; i += 512) {   // 1280 entries
        g_partial[((size_t)pg * B_ + g * RROWS) * NCLS_ + i] = red[i];
    }
    __syncthreads();

    // Last block of this row-group finalizes (threadFenceReduction pattern).
    __shared__ int is_last;
    if (t == 0) {
        __threadfence();
        int old = atomicAdd(&g_cnt[g], 1);
        is_last = (old == PGS - 1);
    }
    __syncthreads();
    if (is_last) {
        __threadfence();   // acquire all 37 partials
        for (int i = t; i < RROWS * NCLS_; i += 512) {
            int n = g * RROWS + i / NCLS_;
            int k = i % NCLS_;
            float sum = bsm[k];
#pragma unroll
            for (int s = 0; s < PGS; s++)      // fixed order: deterministic
                sum += g_partial[((size_t)s * B_ + n) * NCLS_ + k];
            out[n * NCLS_ + k] = sum;
        }
        __syncthreads();
        if (t == 0) g_cnt[g] = 0;              // reset for next (graph) launch
    }
}

// ---------------------------------------------------------------------------
extern "C" void kernel_launch(void* const* d_in, const int* in_sizes, int n_in,
                              void* d_out, int out_size) {
    const float* x     = (const float*)d_in[0];   // [512, 65536]
    const float* W_fgl = (const float*)d_in[1];   // [4, 512]
    const float* b_fgl = (const float*)d_in[2];   // [4, 512]
    const float* W_fc  = (const float*)d_in[3];   // [2048, 10]
    const float* b_fc  = (const float*)d_in[4];   // [10]
    const int*   seg   = (const int*)d_in[5];     // [65536]
    float* out = (float*)d_out;                   // [512, 10]

    cudaFuncSetAttribute(fused_main_k,
                         cudaFuncAttributeMaxDynamicSharedMemorySize, SMEM_TOTAL);

    fused_main_k<<<GRIDM, 512, SMEM_TOTAL>>>(x, seg, W_fgl, b_fgl, W_fc, b_fc, out);
    (void)in_sizes; (void)n_in; (void)out_size;
}